// round 14
// baseline (speedup 1.0000x reference)
#include <cuda_runtime.h>
#include <cuda_fp16.h>
#include <cstdint>

#define NN 100000
#define NE 1600000
#define NG 256
#define D  128
#define DOUT 64

#define SAH 40                   // smem stride in halves (word stride 20: conflict-free)
#define ASTH (128 * SAH)         // halves per A stage
#define BSTH (128 * SAH)         // halves per B stage
#define GEMM_SMEM ((2 * ASTH + 2 * BSTH) * 2)   // 40960 bytes

// ---------------- scratch (static device globals; no allocs) ----------------
__device__ __align__(16) __half g_x16[(size_t)NN * D];
__device__ __align__(16) __half g_h116[(size_t)NN * D];
__device__ __align__(16) __half g_h216[(size_t)NN * D];  // fp16 shadow of h2
__device__ __align__(16) __half g_agg16[(size_t)NN * D];
__device__ __align__(16) float  g_h2[(size_t)NN * D];
__device__ __align__(16) float  g_agg[(size_t)NN * D];
__device__ __align__(16) __half g_w16[4 * D * D];       // fp16 weights, [n][k] layout
__device__ __align__(16) int    g_rowoff[NN + 1];
__device__ __align__(16) int    g_cursor[NN];
__device__ __align__(16) int    g_count[NN];
__device__ __align__(16) int    g_csr[NE];
__device__ __align__(16) float  g_deginv[NN];
__device__ __align__(16) float  g_pool[NG * 2 * D];
__device__ __align__(16) int    g_gstart[NG + 1];
__device__ __align__(16) int    g_bsum[128];

#define SCAN_BLOCKS 98   // 98 * 1024 >= NN

// ---------------- in-degree histogram over dst ----------------
__global__ void k_hist(const int* __restrict__ ei) {
    int e = blockIdx.x * blockDim.x + threadIdx.x;
    if (e < NE) {
        int d = ei[NE + e];
        atomicAdd(&g_count[d], 1);
    }
}

// ---------------- convert x to fp16 ----------------
__global__ void k_xconv(const float* __restrict__ x) {
    int i = blockIdx.x * blockDim.x + threadIdx.x;
    if (i >= NN * D / 4) return;
    float4 v = *(const float4*)(x + (size_t)i * 4);
    __half2 h0 = __floats2half2_rn(v.x, v.y);
    __half2 h1 = __floats2half2_rn(v.z, v.w);
    uint2 pk = make_uint2(*(uint32_t*)&h0, *(uint32_t*)&h1);
    *(uint2*)(g_x16 + (size_t)i * 4) = pk;
}

// ---------------- convert + transpose weights to fp16 [n][k] ----------------
__global__ void k_wconv(const float* __restrict__ W1rel, const float* __restrict__ W1root,
                        const float* __restrict__ W2rel, const float* __restrict__ W2root) {
    int idx = blockIdx.x * blockDim.x + threadIdx.x;   // 0 .. 4*D*D-1
    if (idx >= 4 * D * D) return;
    int m = idx >> 14;
    int rem = idx & 16383;
    int n = rem >> 7, k = rem & 127;
    const float* src = (m == 0) ? W1rel : (m == 1) ? W1root : (m == 2) ? W2rel : W2root;
    g_w16[idx] = __float2half_rn(src[k * D + n]);
}

// ---------------- graph boundaries: streaming detect on sorted batch -------
__global__ void k_gbound(const int* __restrict__ batch) {
    int i = blockIdx.x * blockDim.x + threadIdx.x;
    if (i >= NN) return;
    int b = batch[i];
    if (i == 0)
        for (int g = 0; g <= b; g++) g_gstart[g] = 0;
    int b1 = (i == NN - 1) ? NG : batch[i + 1];
    for (int g = b + 1; g <= b1; g++) g_gstart[g] = i + 1;
}

// ---------------- scan phase A ----------------
__global__ __launch_bounds__(1024) void k_scanA() {
    __shared__ int sc[1024];
    int t = threadIdx.x;
    int idx = blockIdx.x * 1024 + t;
    int v = (idx < NN) ? g_count[idx] : 0;
    sc[t] = v;
    __syncthreads();
    for (int off = 1; off < 1024; off <<= 1) {
        int u = (t >= off) ? sc[t - off] : 0;
        __syncthreads();
        sc[t] += u;
        __syncthreads();
    }
    if (t == 1023) g_bsum[blockIdx.x] = sc[1023];
    if (idx < NN) g_rowoff[idx] = sc[t] - v;
}

// ---------------- scan phase B: scan the 98 block sums (1 block) ----------
__global__ __launch_bounds__(128) void k_scanB() {
    __shared__ int sc[128];
    int t = threadIdx.x;
    int v = (t < SCAN_BLOCKS) ? g_bsum[t] : 0;
    sc[t] = v;
    __syncthreads();
    for (int off = 1; off < 128; off <<= 1) {
        int u = (t >= off) ? sc[t - off] : 0;
        __syncthreads();
        sc[t] += u;
        __syncthreads();
    }
    if (t < SCAN_BLOCKS) g_bsum[t] = sc[t] - v;
}

// ---------------- scan phase C ----------------
__global__ void k_scanC() {
    int idx = blockIdx.x * blockDim.x + threadIdx.x;
    if (idx < NN) {
        int off = g_rowoff[idx] + g_bsum[idx >> 10];
        g_rowoff[idx] = off;
        g_cursor[idx] = off;
        g_deginv[idx] = 1.0f / (float)max(g_count[idx], 1);
        g_count[idx] = 0;
    }
    if (idx == 0) g_rowoff[NN] = NE;
}

// ---------------- CSR fill ----------------
__global__ void k_fill(const int* __restrict__ ei) {
    int e = blockIdx.x * blockDim.x + threadIdx.x;
    if (e < NE) {
        int s = ei[e];
        int d = ei[NE + e];
        int pos = atomicAdd(&g_cursor[d], 1);
        g_csr[pos] = s;
    }
}

// ---------------- gather-mean aggregation, fp16 in, fp16/fp32 out ----------
__global__ void k_agg16(const __half* __restrict__ hin, int out32) {
    int node = (blockIdx.x * blockDim.x + threadIdx.x) >> 5;
    if (node >= NN) return;
    int lane = threadIdx.x & 31;
    int beg = g_rowoff[node], end = g_rowoff[node + 1];
    const __half* base = hin + lane * 4;
    float4 acc = make_float4(0.f, 0.f, 0.f, 0.f);
    for (int e = beg; e < end; e++) {
        int s = g_csr[e];
        uint2 pk = *(const uint2*)(base + (size_t)s * D);
        float2 f0 = __half22float2(*(__half2*)&pk.x);
        float2 f1 = __half22float2(*(__half2*)&pk.y);
        acc.x += f0.x; acc.y += f0.y; acc.z += f1.x; acc.w += f1.y;
    }
    float sc = g_deginv[node];
    acc.x *= sc; acc.y *= sc; acc.z *= sc; acc.w *= sc;
    if (out32) {
        *(float4*)(g_agg + (size_t)node * D + lane * 4) = acc;
    } else {
        __half2 h0 = __floats2half2_rn(acc.x, acc.y);
        __half2 h1 = __floats2half2_rn(acc.z, acc.w);
        uint2 pk = make_uint2(*(uint32_t*)&h0, *(uint32_t*)&h1);
        *(uint2*)(g_agg16 + (size_t)node * D + lane * 4) = pk;
    }
}

// ---------------- cp.async helpers ----------------
__device__ __forceinline__ void cpa16(uint32_t dst, const void* src, uint32_t srcsize) {
    asm volatile("cp.async.cg.shared.global [%0], [%1], 16, %2;"
                 :: "r"(dst), "l"(src), "r"(srcsize) : "memory");
}
__device__ __forceinline__ uint32_t smem_u32(const void* p) {
    uint32_t a;
    asm("{ .reg .u64 t; cvta.to.shared.u64 t, %1; cvt.u32.u64 %0, t; }" : "=r"(a) : "l"(p));
    return a;
}

// ---------------- fused GEMM: fp16 mma, cp.async double-buffered ------------
// out = relu(A0@W0' + A1@W1' + b). A: [node][k] fp16; W: [n][k] fp16.
// mode 0: store fp16 to out16. mode 1: store fp32 to out32 AND fp16 to out16.
__global__ __launch_bounds__(256) void k_gemm16(
    const __half* __restrict__ A0,
    const __half* __restrict__ A1,
    const __half* __restrict__ W0,
    const __half* __restrict__ W1,
    const float* __restrict__ bias,
    float* __restrict__ out32,
    __half* __restrict__ out16,
    int mode32)
{
    extern __shared__ __half smh[];
    int row0 = blockIdx.x * 128;
    int tid  = threadIdx.x;
    int warp = tid >> 5, lane = tid & 31;
    int wm = warp >> 2;
    int wn = warp & 3;
    int r  = lane >> 2;
    int cq = lane & 3;
    uint32_t smbase = smem_u32(smh);

    float acc[4][4][4];
#pragma unroll
    for (int mi = 0; mi < 4; mi++)
#pragma unroll
        for (int ni = 0; ni < 4; ni++)
#pragma unroll
            for (int q = 0; q < 4; q++) acc[mi][ni][q] = 0.f;

    auto load_stage = [&](int s, int kt) {
        const __half* srcA = (kt < 4) ? A0 : A1;
        const __half* W    = (kt < 4) ? W0 : W1;
        int kc = (kt * 32) & 127;
        uint32_t aBase = smbase + (uint32_t)(s * ASTH) * 2;
        uint32_t bBase = smbase + (uint32_t)(2 * ASTH + s * BSTH) * 2;
#pragma unroll
        for (int i = 0; i < 2; i++) {
            int c = tid + i * 256;
            int row = c >> 2, q = c & 3;
            int grow = row0 + row;
            int ok = (grow < NN);
            const __half* p = srcA + (size_t)(ok ? grow : 0) * D + kc + q * 8;
            cpa16(aBase + (uint32_t)(row * SAH + q * 8) * 2, p, ok ? 16u : 0u);
        }
#pragma unroll
        for (int i = 0; i < 2; i++) {
            int c = tid + i * 256;
            int n = c >> 2, q = c & 3;
            const __half* p = W + (size_t)n * D + kc + q * 8;
            cpa16(bBase + (uint32_t)(n * SAH + q * 8) * 2, p, 16u);
        }
        asm volatile("cp.async.commit_group;" ::: "memory");
    };

    load_stage(0, 0);
    load_stage(1, 1);

#pragma unroll 1
    for (int kt = 0; kt < 8; kt++) {
        if (kt < 7) asm volatile("cp.async.wait_group 1;" ::: "memory");
        else        asm volatile("cp.async.wait_group 0;" ::: "memory");
        __syncthreads();

        int s = kt & 1;
        const __half* as_ = smh + s * ASTH;
        const __half* bs_ = smh + 2 * ASTH + s * BSTH;
#pragma unroll
        for (int ks = 0; ks < 32; ks += 16) {
            int kf = ks + 2 * cq;
            uint32_t bf[4][2];
#pragma unroll
            for (int ni = 0; ni < 4; ni++) {
                int n = wn * 32 + ni * 8 + r;
                bf[ni][0] = *(const uint32_t*)(bs_ + n * SAH + kf);
                bf[ni][1] = *(const uint32_t*)(bs_ + n * SAH + kf + 8);
            }
#pragma unroll
            for (int mi = 0; mi < 4; mi++) {
                int row = wm * 64 + mi * 16 + r;
                uint32_t a0 = *(const uint32_t*)(as_ + row * SAH + kf);
                uint32_t a1 = *(const uint32_t*)(as_ + (row + 8) * SAH + kf);
                uint32_t a2 = *(const uint32_t*)(as_ + row * SAH + kf + 8);
                uint32_t a3 = *(const uint32_t*)(as_ + (row + 8) * SAH + kf + 8);
#pragma unroll
                for (int ni = 0; ni < 4; ni++) {
                    asm volatile(
                        "mma.sync.aligned.m16n8k16.row.col.f32.f16.f16.f32 "
                        "{%0,%1,%2,%3}, {%4,%5,%6,%7}, {%8,%9}, {%0,%1,%2,%3};"
                        : "+f"(acc[mi][ni][0]), "+f"(acc[mi][ni][1]),
                          "+f"(acc[mi][ni][2]), "+f"(acc[mi][ni][3])
                        : "r"(a0), "r"(a1), "r"(a2), "r"(a3),
                          "r"(bf[ni][0]), "r"(bf[ni][1]));
                }
            }
        }
        __syncthreads();
        if (kt + 2 < 8) load_stage(s, kt + 2);
    }

    // epilogue: bias + relu; store fp16 (+fp32 when mode32)
#pragma unroll
    for (int mi = 0; mi < 4; mi++) {
        int r0g = row0 + wm * 64 + mi * 16 + r;
        int r1g = r0g + 8;
#pragma unroll
        for (int ni = 0; ni < 4; ni++) {
            int col = wn * 32 + ni * 8 + 2 * cq;
            float bz0 = bias[col], bz1 = bias[col + 1];
            float v0 = fmaxf(acc[mi][ni][0] + bz0, 0.f);
            float v1 = fmaxf(acc[mi][ni][1] + bz1, 0.f);
            float v2 = fmaxf(acc[mi][ni][2] + bz0, 0.f);
            float v3 = fmaxf(acc[mi][ni][3] + bz1, 0.f);
            if (r0g < NN) {
                __half2 h = __floats2half2_rn(v0, v1);
                *(uint32_t*)(out16 + (size_t)r0g * D + col) = *(uint32_t*)&h;
                if (mode32)
                    *(float2*)(out32 + (size_t)r0g * D + col) = make_float2(v0, v1);
            }
            if (r1g < NN) {
                __half2 h = __floats2half2_rn(v2, v3);
                *(uint32_t*)(out16 + (size_t)r1g * D + col) = *(uint32_t*)&h;
                if (mode32)
                    *(float2*)(out32 + (size_t)r1g * D + col) = make_float2(v2, v3);
            }
        }
    }
}

// ---------------- pooling ----------------
__global__ __launch_bounds__(128) void k_pool() {
    int g = blockIdx.x;
    int n = threadIdx.x;
    int beg = g_gstart[g], end = g_gstart[g + 1];
    float sa = 0.f, sh = 0.f;
    for (int node = beg; node < end; node++) {
        sa += g_agg[(size_t)node * D + n];
        sh += g_h2[(size_t)node * D + n];
    }
    int cnt = end - beg;
    float cinv = 1.0f / (float)max(cnt, 1);
    g_pool[g * 2 * D + n]     = sa * cinv;
    g_pool[g * 2 * D + D + n] = sh * cinv;
}

// ---------------- final head (fp32) ----------------
__global__ void k_final(const float* __restrict__ W3rel,
                        const float* __restrict__ W3root,
                        const float* __restrict__ b3,
                        const float* __restrict__ Wl,
                        const float* __restrict__ bl,
                        float* __restrict__ out)
{
    __shared__ float pa[128], ph[128], t[128];
    int g = blockIdx.x, n = threadIdx.x;
    int cnt = g_gstart[g + 1] - g_gstart[g];
    float bsel = (cnt > 0) ? 1.0f : 0.0f;
    pa[n] = g_pool[g * 2 * D + n];
    ph[n] = g_pool[g * 2 * D + D + n];
    __syncthreads();
    float acc = b3[n] * bsel;
#pragma unroll 8
    for (int k = 0; k < 128; k++)
        acc += pa[k] * W3rel[k * D + n] + ph[k] * W3root[k * D + n];
    t[n] = acc;
    __syncthreads();
    if (n < DOUT) {
        float o = bl[n];
#pragma unroll 8
        for (int k = 0; k < 128; k++)
            o += t[k] * Wl[k * DOUT + n];
        out[g * DOUT + n] = o;
    }
}

// ---------------- launcher ----------------
extern "C" void kernel_launch(void* const* d_in, const int* in_sizes, int n_in,
                              void* d_out, int out_size) {
    const float* x      = (const float*)d_in[0];
    const int*   ei     = (const int*)d_in[1];
    const int*   batch  = (const int*)d_in[2];
    const float* W1rel  = (const float*)d_in[3];
    const float* b1     = (const float*)d_in[4];
    const float* W1root = (const float*)d_in[5];
    const float* W2rel  = (const float*)d_in[6];
    const float* b2     = (const float*)d_in[7];
    const float* W2root = (const float*)d_in[8];
    const float* W3rel  = (const float*)d_in[9];
    const float* b3     = (const float*)d_in[10];
    const float* W3root = (const float*)d_in[11];
    const float* Wl     = (const float*)d_in[12];
    const float* bl     = (const float*)d_in[13];
    float*       out    = (float*)d_out;

    __half *x16, *h116, *h216, *agg16, *w16;
    float *h2;
    cudaGetSymbolAddress((void**)&x16, g_x16);
    cudaGetSymbolAddress((void**)&h116, g_h116);
    cudaGetSymbolAddress((void**)&h216, g_h216);
    cudaGetSymbolAddress((void**)&agg16, g_agg16);
    cudaGetSymbolAddress((void**)&w16, g_w16);
    cudaGetSymbolAddress((void**)&h2, g_h2);

    static int smem_set = 0;
    if (!smem_set) {
        cudaFuncSetAttribute(k_gemm16, cudaFuncAttributeMaxDynamicSharedMemorySize, GEMM_SMEM);
        smem_set = 1;
    }

    const int TB = 256;
    int gbN = (NN + TB - 1) / TB;
    int gbE = (NE + TB - 1) / TB;
    int gbW = (NN * 32 + TB - 1) / TB;
    int gbM = (NN + 127) / 128;
    int gbX = (NN * D / 4 + TB - 1) / TB;
    int gbWc = (4 * D * D + TB - 1) / TB;

    k_hist<<<gbE, TB>>>(ei);
    k_xconv<<<gbX, TB>>>(x);
    k_wconv<<<gbWc, TB>>>(W1rel, W1root, W2rel, W2root);
    k_gbound<<<gbN, TB>>>(batch);
    k_scanA<<<SCAN_BLOCKS, 1024>>>();
    k_scanB<<<1, 128>>>();
    k_scanC<<<gbN, TB>>>();
    k_fill<<<gbE, TB>>>(ei);

    // layer 1: fp16 agg over x16 -> fp16 gemm -> h1 fp16
    k_agg16<<<gbW, TB>>>(x16, 0);
    k_gemm16<<<gbM, TB, GEMM_SMEM>>>(agg16, x16, w16, w16 + D * D, b1, nullptr, h116, 0);
    // layer 2: fp16 agg over h116 -> fp16 gemm -> h2 fp32 + fp16 shadow
    k_agg16<<<gbW, TB>>>(h116, 0);
    k_gemm16<<<gbM, TB, GEMM_SMEM>>>(agg16, h116, w16 + 2 * D * D, w16 + 3 * D * D, b2, h2, h216, 1);
    // layer 3: fp16 gather over h216, fp32 agg out (feeds fp32 pooled head)
    k_agg16<<<gbW, TB>>>(h216, 1);
    k_pool<<<NG, 128>>>();
    k_final<<<NG, 128>>>(W3rel, W3root, b3, Wl, bl, out);
}

// round 15
// speedup vs baseline: 1.2030x; 1.2030x over previous
#include <cuda_runtime.h>
#include <cuda_fp16.h>
#include <cstdint>

#define NN 100000
#define NE 1600000
#define NG 256
#define D  128
#define DOUT 64

#define SAH 40                   // smem stride in halves (word stride 20: conflict-free)
#define ASTH (128 * SAH)
#define BSTH (128 * SAH)
#define GEMM_SMEM ((2 * ASTH + 2 * BSTH) * 2)   // 40960 bytes

#define SCAN_BLOCKS 98           // 98 * 1024 >= NN

// grid partition for the fused setup kernel
#define GB_HIST 6250             // NE / 256
#define GB_X    12500            // NN*D/4 / 256
#define GB_W    256              // 4*D*D / 256
#define GB_GB   391              // ceil(NN/256)
#define GB_SETUP (GB_HIST + GB_X + GB_W + GB_GB + 1)

// ---------------- scratch (static device globals; no allocs) ----------------
__device__ __align__(16) __half g_x16[(size_t)NN * D];
__device__ __align__(16) __half g_h116[(size_t)NN * D];
__device__ __align__(16) __half g_h216[(size_t)NN * D];
__device__ __align__(16) __half g_agg16[(size_t)NN * D];
__device__ __align__(16) __half g_w16[4 * D * D];       // fp16 weights, [n][k]
__device__ __align__(16) int    g_rowoff[NN + 1];
__device__ __align__(16) int    g_cursor[NN];
__device__ __align__(16) int    g_count[NN];
__device__ __align__(16) int    g_csr[NE];
__device__ __align__(16) float  g_deginv[NN];
__device__ __align__(16) int    g_gstart[NG + 1];
__device__ __align__(16) unsigned long long g_scanst[SCAN_BLOCKS];

// ---------------- fused setup: hist + xconv + wconv + gbound + state zero ---
__global__ void k_setup(const int* __restrict__ ei, const float* __restrict__ x,
                        const float* __restrict__ W1rel, const float* __restrict__ W1root,
                        const float* __restrict__ W2rel, const float* __restrict__ W2root,
                        const int* __restrict__ batch) {
    int b = blockIdx.x;
    int t = threadIdx.x;
    if (b < GB_HIST) {
        int e = b * 256 + t;
        if (e < NE) atomicAdd(&g_count[ei[NE + e]], 1);
    } else if (b < GB_HIST + GB_X) {
        int i = (b - GB_HIST) * 256 + t;
        if (i < NN * D / 4) {
            float4 v = *(const float4*)(x + (size_t)i * 4);
            __half2 h0 = __floats2half2_rn(v.x, v.y);
            __half2 h1 = __floats2half2_rn(v.z, v.w);
            uint2 pk = make_uint2(*(uint32_t*)&h0, *(uint32_t*)&h1);
            *(uint2*)(g_x16 + (size_t)i * 4) = pk;
        }
    } else if (b < GB_HIST + GB_X + GB_W) {
        int idx = (b - GB_HIST - GB_X) * 256 + t;   // 0 .. 65535
        int m = idx >> 14;
        int rem = idx & 16383;
        int n = rem >> 7, k = rem & 127;
        const float* src = (m == 0) ? W1rel : (m == 1) ? W1root : (m == 2) ? W2rel : W2root;
        g_w16[idx] = __float2half_rn(src[k * D + n]);
    } else if (b < GB_HIST + GB_X + GB_W + GB_GB) {
        int i = (b - GB_HIST - GB_X - GB_W) * 256 + t;
        if (i < NN) {
            int bb = batch[i];
            if (i == 0)
                for (int g = 0; g <= bb; g++) g_gstart[g] = 0;
            int b1 = (i == NN - 1) ? NG : batch[i + 1];
            for (int g = bb + 1; g <= b1; g++) g_gstart[g] = i + 1;
        }
    } else {
        if (t < SCAN_BLOCKS) g_scanst[t] = 0ull;
    }
}

// ---------------- single-pass scan (decoupled lookback) --------------------
// Produces rowoff/cursor/deginv; re-zeros g_count (replay-safe).
__global__ __launch_bounds__(1024) void k_scan() {
    __shared__ int sc[1024];
    __shared__ int s_off;
    int t = threadIdx.x, b = blockIdx.x;
    int idx = b * 1024 + t;
    int v = (idx < NN) ? g_count[idx] : 0;
    sc[t] = v;
    __syncthreads();
    for (int off = 1; off < 1024; off <<= 1) {
        int u = (t >= off) ? sc[t - off] : 0;
        __syncthreads();
        sc[t] += u;
        __syncthreads();
    }
    int total = sc[1023];
    if (t == 0) {
        const unsigned long long VMASK = 0x3FFFFFFFFFFFFFFFull;
        if (b == 0) {
            atomicExch(&g_scanst[0], (2ull << 62) | (unsigned long long)(unsigned)total);
            s_off = 0;
        } else {
            atomicExch(&g_scanst[b], (1ull << 62) | (unsigned long long)(unsigned)total);
            unsigned long long run = 0;
            int j = b - 1;
            while (true) {
                unsigned long long s = atomicAdd(&g_scanst[j], 0ull);
                unsigned long long tag = s >> 62;
                if (tag == 2ull) { run += (s & VMASK); break; }
                if (tag == 1ull) { run += (s & VMASK); j--; }
                // tag 0: spin (all 98 blocks co-resident on 148 SMs)
            }
            s_off = (int)run;
            atomicExch(&g_scanst[b], (2ull << 62) | (run + (unsigned long long)(unsigned)total));
        }
    }
    __syncthreads();
    if (idx < NN) {
        int off = s_off + sc[t] - v;      // exclusive prefix
        g_rowoff[idx] = off;
        g_cursor[idx] = off;
        g_deginv[idx] = 1.0f / (float)max(v, 1);
        g_count[idx] = 0;
    }
    if (idx == 0) g_rowoff[NN] = NE;
}

// ---------------- CSR fill ----------------
__global__ void k_fill(const int* __restrict__ ei) {
    int e = blockIdx.x * blockDim.x + threadIdx.x;
    if (e < NE) {
        int s = ei[e];
        int d = ei[NE + e];
        int pos = atomicAdd(&g_cursor[d], 1);
        g_csr[pos] = s;
    }
}

// ---------------- gather-mean aggregation: fp16 in, fp16 out ----------------
__global__ void k_agg16(const __half* __restrict__ hin) {
    int node = (blockIdx.x * blockDim.x + threadIdx.x) >> 5;
    if (node >= NN) return;
    int lane = threadIdx.x & 31;
    int beg = g_rowoff[node], end = g_rowoff[node + 1];
    const __half* base = hin + lane * 4;
    float4 acc = make_float4(0.f, 0.f, 0.f, 0.f);
    for (int e = beg; e < end; e++) {
        int s = g_csr[e];
        uint2 pk = *(const uint2*)(base + (size_t)s * D);
        float2 f0 = __half22float2(*(__half2*)&pk.x);
        float2 f1 = __half22float2(*(__half2*)&pk.y);
        acc.x += f0.x; acc.y += f0.y; acc.z += f1.x; acc.w += f1.y;
    }
    float sc = g_deginv[node];
    __half2 h0 = __floats2half2_rn(acc.x * sc, acc.y * sc);
    __half2 h1 = __floats2half2_rn(acc.z * sc, acc.w * sc);
    uint2 pk = make_uint2(*(uint32_t*)&h0, *(uint32_t*)&h1);
    *(uint2*)(g_agg16 + (size_t)node * D + lane * 4) = pk;
}

// ---------------- cp.async helpers ----------------
__device__ __forceinline__ void cpa16(uint32_t dst, const void* src, uint32_t srcsize) {
    asm volatile("cp.async.cg.shared.global [%0], [%1], 16, %2;"
                 :: "r"(dst), "l"(src), "r"(srcsize) : "memory");
}
__device__ __forceinline__ uint32_t smem_u32(const void* p) {
    uint32_t a;
    asm("{ .reg .u64 t; cvta.to.shared.u64 t, %1; cvt.u32.u64 %0, t; }" : "=r"(a) : "l"(p));
    return a;
}

// ---------------- fused GEMM: fp16 mma, cp.async double-buffered ------------
// out16 = relu(A0@W0' + A1@W1' + b). A: [node][k] fp16; W: [n][k] fp16.
__global__ __launch_bounds__(256) void k_gemm16(
    const __half* __restrict__ A0,
    const __half* __restrict__ A1,
    const __half* __restrict__ W0,
    const __half* __restrict__ W1,
    const float* __restrict__ bias,
    __half* __restrict__ out16)
{
    extern __shared__ __half smh[];
    int row0 = blockIdx.x * 128;
    int tid  = threadIdx.x;
    int warp = tid >> 5, lane = tid & 31;
    int wm = warp >> 2;
    int wn = warp & 3;
    int r  = lane >> 2;
    int cq = lane & 3;
    uint32_t smbase = smem_u32(smh);

    float acc[4][4][4];
#pragma unroll
    for (int mi = 0; mi < 4; mi++)
#pragma unroll
        for (int ni = 0; ni < 4; ni++)
#pragma unroll
            for (int q = 0; q < 4; q++) acc[mi][ni][q] = 0.f;

    auto load_stage = [&](int s, int kt) {
        const __half* srcA = (kt < 4) ? A0 : A1;
        const __half* W    = (kt < 4) ? W0 : W1;
        int kc = (kt * 32) & 127;
        uint32_t aBase = smbase + (uint32_t)(s * ASTH) * 2;
        uint32_t bBase = smbase + (uint32_t)(2 * ASTH + s * BSTH) * 2;
#pragma unroll
        for (int i = 0; i < 2; i++) {
            int c = tid + i * 256;
            int row = c >> 2, q = c & 3;
            int grow = row0 + row;
            int ok = (grow < NN);
            const __half* p = srcA + (size_t)(ok ? grow : 0) * D + kc + q * 8;
            cpa16(aBase + (uint32_t)(row * SAH + q * 8) * 2, p, ok ? 16u : 0u);
        }
#pragma unroll
        for (int i = 0; i < 2; i++) {
            int c = tid + i * 256;
            int n = c >> 2, q = c & 3;
            const __half* p = W + (size_t)n * D + kc + q * 8;
            cpa16(bBase + (uint32_t)(n * SAH + q * 8) * 2, p, 16u);
        }
        asm volatile("cp.async.commit_group;" ::: "memory");
    };

    load_stage(0, 0);
    load_stage(1, 1);

#pragma unroll 1
    for (int kt = 0; kt < 8; kt++) {
        if (kt < 7) asm volatile("cp.async.wait_group 1;" ::: "memory");
        else        asm volatile("cp.async.wait_group 0;" ::: "memory");
        __syncthreads();

        int s = kt & 1;
        const __half* as_ = smh + s * ASTH;
        const __half* bs_ = smh + 2 * ASTH + s * BSTH;
#pragma unroll
        for (int ks = 0; ks < 32; ks += 16) {
            int kf = ks + 2 * cq;
            uint32_t bf[4][2];
#pragma unroll
            for (int ni = 0; ni < 4; ni++) {
                int n = wn * 32 + ni * 8 + r;
                bf[ni][0] = *(const uint32_t*)(bs_ + n * SAH + kf);
                bf[ni][1] = *(const uint32_t*)(bs_ + n * SAH + kf + 8);
            }
#pragma unroll
            for (int mi = 0; mi < 4; mi++) {
                int row = wm * 64 + mi * 16 + r;
                uint32_t a0 = *(const uint32_t*)(as_ + row * SAH + kf);
                uint32_t a1 = *(const uint32_t*)(as_ + (row + 8) * SAH + kf);
                uint32_t a2 = *(const uint32_t*)(as_ + row * SAH + kf + 8);
                uint32_t a3 = *(const uint32_t*)(as_ + (row + 8) * SAH + kf + 8);
#pragma unroll
                for (int ni = 0; ni < 4; ni++) {
                    asm volatile(
                        "mma.sync.aligned.m16n8k16.row.col.f32.f16.f16.f32 "
                        "{%0,%1,%2,%3}, {%4,%5,%6,%7}, {%8,%9}, {%0,%1,%2,%3};"
                        : "+f"(acc[mi][ni][0]), "+f"(acc[mi][ni][1]),
                          "+f"(acc[mi][ni][2]), "+f"(acc[mi][ni][3])
                        : "r"(a0), "r"(a1), "r"(a2), "r"(a3),
                          "r"(bf[ni][0]), "r"(bf[ni][1]));
                }
            }
        }
        __syncthreads();
        if (kt + 2 < 8) load_stage(s, kt + 2);
    }

#pragma unroll
    for (int mi = 0; mi < 4; mi++) {
        int r0g = row0 + wm * 64 + mi * 16 + r;
        int r1g = r0g + 8;
#pragma unroll
        for (int ni = 0; ni < 4; ni++) {
            int col = wn * 32 + ni * 8 + 2 * cq;
            float bz0 = bias[col], bz1 = bias[col + 1];
            float v0 = fmaxf(acc[mi][ni][0] + bz0, 0.f);
            float v1 = fmaxf(acc[mi][ni][1] + bz1, 0.f);
            float v2 = fmaxf(acc[mi][ni][2] + bz0, 0.f);
            float v3 = fmaxf(acc[mi][ni][3] + bz1, 0.f);
            if (r0g < NN) {
                __half2 h = __floats2half2_rn(v0, v1);
                *(uint32_t*)(out16 + (size_t)r0g * D + col) = *(uint32_t*)&h;
            }
            if (r1g < NN) {
                __half2 h = __floats2half2_rn(v2, v3);
                *(uint32_t*)(out16 + (size_t)r1g * D + col) = *(uint32_t*)&h;
            }
        }
    }
}

// ---------------- fused pooling + layer3 head + linear ----------------------
// block g: mean-pool agg3 (g_agg16) and h2 (g_h216) over the graph's nodes,
// then out[g] = (pa@W3rel + ph@W3root + b3) @ Wl + bl, all fp32.
__global__ __launch_bounds__(128) void k_poolfinal(
    const float* __restrict__ W3rel,
    const float* __restrict__ W3root,
    const float* __restrict__ b3,
    const float* __restrict__ Wl,
    const float* __restrict__ bl,
    float* __restrict__ out)
{
    __shared__ float pa[128], ph[128], t[128];
    int g = blockIdx.x, n = threadIdx.x;
    int beg = g_gstart[g], end = g_gstart[g + 1];
    float sa = 0.f, sh = 0.f;
    for (int node = beg; node < end; node++) {
        sa += __half2float(g_agg16[(size_t)node * D + n]);
        sh += __half2float(g_h216[(size_t)node * D + n]);
    }
    int cnt = end - beg;
    float cinv = 1.0f / (float)max(cnt, 1);
    float bsel = (cnt > 0) ? 1.0f : 0.0f;
    pa[n] = sa * cinv;
    ph[n] = sh * cinv;
    __syncthreads();
    float acc = b3[n] * bsel;
#pragma unroll 8
    for (int k = 0; k < 128; k++)
        acc += pa[k] * W3rel[k * D + n] + ph[k] * W3root[k * D + n];
    t[n] = acc;
    __syncthreads();
    if (n < DOUT) {
        float o = bl[n];
#pragma unroll 8
        for (int k = 0; k < 128; k++)
            o += t[k] * Wl[k * DOUT + n];
        out[g * DOUT + n] = o;
    }
}

// ---------------- launcher ----------------
extern "C" void kernel_launch(void* const* d_in, const int* in_sizes, int n_in,
                              void* d_out, int out_size) {
    const float* x      = (const float*)d_in[0];
    const int*   ei     = (const int*)d_in[1];
    const int*   batch  = (const int*)d_in[2];
    const float* W1rel  = (const float*)d_in[3];
    const float* b1     = (const float*)d_in[4];
    const float* W1root = (const float*)d_in[5];
    const float* W2rel  = (const float*)d_in[6];
    const float* b2     = (const float*)d_in[7];
    const float* W2root = (const float*)d_in[8];
    const float* W3rel  = (const float*)d_in[9];
    const float* b3     = (const float*)d_in[10];
    const float* W3root = (const float*)d_in[11];
    const float* Wl     = (const float*)d_in[12];
    const float* bl     = (const float*)d_in[13];
    float*       out    = (float*)d_out;

    __half *x16, *h116, *h216, *agg16, *w16;
    cudaGetSymbolAddress((void**)&x16, g_x16);
    cudaGetSymbolAddress((void**)&h116, g_h116);
    cudaGetSymbolAddress((void**)&h216, g_h216);
    cudaGetSymbolAddress((void**)&agg16, g_agg16);
    cudaGetSymbolAddress((void**)&w16, g_w16);

    static int smem_set = 0;
    if (!smem_set) {
        cudaFuncSetAttribute(k_gemm16, cudaFuncAttributeMaxDynamicSharedMemorySize, GEMM_SMEM);
        smem_set = 1;
    }

    const int TB = 256;
    int gbE = (NE + TB - 1) / TB;
    int gbW = (NN * 32 + TB - 1) / TB;
    int gbM = (NN + 127) / 128;

    // 1: fused setup (hist, x->fp16, W->fp16[n][k], graph bounds, scan-state zero)
    k_setup<<<GB_SETUP, TB>>>(ei, x, W1rel, W1root, W2rel, W2root, batch);
    // 2: single-pass decoupled-lookback scan -> rowoff/cursor/deginv
    k_scan<<<SCAN_BLOCKS, 1024>>>();
    // 3: CSR fill
    k_fill<<<gbE, TB>>>(ei);
    // 4: layer-1 aggregation (profiled slot)
    k_agg16<<<gbW, TB>>>(x16);
    // 5: layer-1 gemm -> h1 fp16
    k_gemm16<<<gbM, TB, GEMM_SMEM>>>(agg16, x16, w16, w16 + D * D, b1, h116);
    // 6: layer-2 aggregation
    k_agg16<<<gbW, TB>>>(h116);
    // 7: layer-2 gemm -> h2 fp16
    k_gemm16<<<gbM, TB, GEMM_SMEM>>>(agg16, h116, w16 + 2 * D * D, w16 + 3 * D * D, b2, h216);
    // 8: layer-3 aggregation
    k_agg16<<<gbW, TB>>>(h216);
    // 9: fused pool + head
    k_poolfinal<<<NG, 128>>>(W3rel, W3root, b3, Wl, bl, out);
}

// round 16
// speedup vs baseline: 1.2216x; 1.0155x over previous
#include <cuda_runtime.h>
#include <cuda_fp16.h>
#include <cstdint>

#define NN 100000
#define NE 1600000
#define NG 256
#define D  128
#define DOUT 64

#define SAH 40                   // smem stride in halves (word stride 20: conflict-free)
#define ASTH (128 * SAH)
#define BSTH (128 * SAH)
#define GEMM_SMEM ((2 * ASTH + 2 * BSTH) * 2)   // 40960 bytes

#define SCAN_BLOCKS 98           // 98 * 1024 >= NN

// grid partition for the fused setup kernel
#define GB_HIST 6250             // NE / 256
#define GB_X    12500            // NN*D/4 / 256
#define GB_W    256              // 4*D*D / 256
#define GB_GB   391              // ceil(NN/256)
#define GB_SETUP (GB_HIST + GB_X + GB_W + GB_GB + 1)

// ---------------- scratch (static device globals; no allocs) ----------------
__device__ __align__(16) __half g_x16[(size_t)NN * D];
__device__ __align__(16) __half g_h116[(size_t)NN * D];
__device__ __align__(16) __half g_h216[(size_t)NN * D];
__device__ __align__(16) __half g_agg16[(size_t)NN * D];
__device__ __align__(16) __half g_w16[4 * D * D];       // fp16 weights, [n][k]
__device__ __align__(16) int    g_rowoff[NN + 1];
__device__ __align__(16) int    g_cursor[NN];
__device__ __align__(16) int    g_count[NN];
__device__ __align__(16) int    g_csr[NE];
__device__ __align__(16) float  g_deginv[NN];
__device__ __align__(16) int    g_gstart[NG + 1];
__device__ __align__(16) unsigned long long g_scanst[SCAN_BLOCKS];

// ---------------- fused setup: hist + xconv + wconv + gbound + state zero ---
__global__ void k_setup(const int* __restrict__ ei, const float* __restrict__ x,
                        const float* __restrict__ W1rel, const float* __restrict__ W1root,
                        const float* __restrict__ W2rel, const float* __restrict__ W2root,
                        const int* __restrict__ batch) {
    int b = blockIdx.x;
    int t = threadIdx.x;
    if (b < GB_HIST) {
        int e = b * 256 + t;
        if (e < NE) atomicAdd(&g_count[ei[NE + e]], 1);
    } else if (b < GB_HIST + GB_X) {
        int i = (b - GB_HIST) * 256 + t;
        if (i < NN * D / 4) {
            float4 v = *(const float4*)(x + (size_t)i * 4);
            __half2 h0 = __floats2half2_rn(v.x, v.y);
            __half2 h1 = __floats2half2_rn(v.z, v.w);
            uint2 pk = make_uint2(*(uint32_t*)&h0, *(uint32_t*)&h1);
            *(uint2*)(g_x16 + (size_t)i * 4) = pk;
        }
    } else if (b < GB_HIST + GB_X + GB_W) {
        int idx = (b - GB_HIST - GB_X) * 256 + t;   // 0 .. 65535
        int m = idx >> 14;
        int rem = idx & 16383;
        int n = rem >> 7, k = rem & 127;
        const float* src = (m == 0) ? W1rel : (m == 1) ? W1root : (m == 2) ? W2rel : W2root;
        g_w16[idx] = __float2half_rn(src[k * D + n]);
    } else if (b < GB_HIST + GB_X + GB_W + GB_GB) {
        int i = (b - GB_HIST - GB_X - GB_W) * 256 + t;
        if (i < NN) {
            int bb = batch[i];
            if (i == 0)
                for (int g = 0; g <= bb; g++) g_gstart[g] = 0;
            int b1 = (i == NN - 1) ? NG : batch[i + 1];
            for (int g = bb + 1; g <= b1; g++) g_gstart[g] = i + 1;
        }
    } else {
        if (t < SCAN_BLOCKS) g_scanst[t] = 0ull;
    }
}

// ---------------- single-pass scan (decoupled lookback) --------------------
__global__ __launch_bounds__(1024) void k_scan() {
    __shared__ int sc[1024];
    __shared__ int s_off;
    int t = threadIdx.x, b = blockIdx.x;
    int idx = b * 1024 + t;
    int v = (idx < NN) ? g_count[idx] : 0;
    sc[t] = v;
    __syncthreads();
    for (int off = 1; off < 1024; off <<= 1) {
        int u = (t >= off) ? sc[t - off] : 0;
        __syncthreads();
        sc[t] += u;
        __syncthreads();
    }
    int total = sc[1023];
    if (t == 0) {
        const unsigned long long VMASK = 0x3FFFFFFFFFFFFFFFull;
        if (b == 0) {
            atomicExch(&g_scanst[0], (2ull << 62) | (unsigned long long)(unsigned)total);
            s_off = 0;
        } else {
            atomicExch(&g_scanst[b], (1ull << 62) | (unsigned long long)(unsigned)total);
            unsigned long long run = 0;
            int j = b - 1;
            while (true) {
                unsigned long long s = atomicAdd(&g_scanst[j], 0ull);
                unsigned long long tag = s >> 62;
                if (tag == 2ull) { run += (s & VMASK); break; }
                if (tag == 1ull) { run += (s & VMASK); j--; }
            }
            s_off = (int)run;
            atomicExch(&g_scanst[b], (2ull << 62) | (run + (unsigned long long)(unsigned)total));
        }
    }
    __syncthreads();
    if (idx < NN) {
        int off = s_off + sc[t] - v;
        g_rowoff[idx] = off;
        g_cursor[idx] = off;
        g_deginv[idx] = 1.0f / (float)max(v, 1);
        g_count[idx] = 0;
    }
    if (idx == 0) g_rowoff[NN] = NE;
}

// ---------------- CSR fill ----------------
__global__ void k_fill(const int* __restrict__ ei) {
    int e = blockIdx.x * blockDim.x + threadIdx.x;
    if (e < NE) {
        int s = ei[e];
        int d = ei[NE + e];
        int pos = atomicAdd(&g_cursor[d], 1);
        g_csr[pos] = s;
    }
}

// ---------------- gather-mean aggregation: fp16 pair-add, 2-edge unroll -----
// One warp per node; lane covers 4 features. Two edges per iteration:
// rows combined with HADD2 (one fp16 add level), then converted + fp32 accum.
__global__ void k_agg16(const __half* __restrict__ hin) {
    int node = (blockIdx.x * blockDim.x + threadIdx.x) >> 5;
    if (node >= NN) return;
    int lane = threadIdx.x & 31;
    int beg = g_rowoff[node], end = g_rowoff[node + 1];
    const __half* base = hin + lane * 4;
    float4 acc = make_float4(0.f, 0.f, 0.f, 0.f);
    int e = beg;
    for (; e + 2 <= end; e += 2) {
        int s0 = g_csr[e];
        int s1 = g_csr[e + 1];
        uint2 p0 = *(const uint2*)(base + (size_t)s0 * D);
        uint2 p1 = *(const uint2*)(base + (size_t)s1 * D);
        __half2 a0 = __hadd2(*(__half2*)&p0.x, *(__half2*)&p1.x);
        __half2 a1 = __hadd2(*(__half2*)&p0.y, *(__half2*)&p1.y);
        float2 f0 = __half22float2(a0);
        float2 f1 = __half22float2(a1);
        acc.x += f0.x; acc.y += f0.y; acc.z += f1.x; acc.w += f1.y;
    }
    if (e < end) {
        int s = g_csr[e];
        uint2 pk = *(const uint2*)(base + (size_t)s * D);
        float2 f0 = __half22float2(*(__half2*)&pk.x);
        float2 f1 = __half22float2(*(__half2*)&pk.y);
        acc.x += f0.x; acc.y += f0.y; acc.z += f1.x; acc.w += f1.y;
    }
    float sc = g_deginv[node];
    __half2 h0 = __floats2half2_rn(acc.x * sc, acc.y * sc);
    __half2 h1 = __floats2half2_rn(acc.z * sc, acc.w * sc);
    uint2 pk = make_uint2(*(uint32_t*)&h0, *(uint32_t*)&h1);
    *(uint2*)(g_agg16 + (size_t)node * D + lane * 4) = pk;
}

// ---------------- cp.async helpers ----------------
__device__ __forceinline__ void cpa16(uint32_t dst, const void* src, uint32_t srcsize) {
    asm volatile("cp.async.cg.shared.global [%0], [%1], 16, %2;"
                 :: "r"(dst), "l"(src), "r"(srcsize) : "memory");
}
__device__ __forceinline__ uint32_t smem_u32(const void* p) {
    uint32_t a;
    asm("{ .reg .u64 t; cvta.to.shared.u64 t, %1; cvt.u32.u64 %0, t; }" : "=r"(a) : "l"(p));
    return a;
}

// ---------------- fused GEMM: fp16 mma, cp.async double-buffered ------------
__global__ __launch_bounds__(256) void k_gemm16(
    const __half* __restrict__ A0,
    const __half* __restrict__ A1,
    const __half* __restrict__ W0,
    const __half* __restrict__ W1,
    const float* __restrict__ bias,
    __half* __restrict__ out16)
{
    extern __shared__ __half smh[];
    int row0 = blockIdx.x * 128;
    int tid  = threadIdx.x;
    int warp = tid >> 5, lane = tid & 31;
    int wm = warp >> 2;
    int wn = warp & 3;
    int r  = lane >> 2;
    int cq = lane & 3;
    uint32_t smbase = smem_u32(smh);

    float acc[4][4][4];
#pragma unroll
    for (int mi = 0; mi < 4; mi++)
#pragma unroll
        for (int ni = 0; ni < 4; ni++)
#pragma unroll
            for (int q = 0; q < 4; q++) acc[mi][ni][q] = 0.f;

    auto load_stage = [&](int s, int kt) {
        const __half* srcA = (kt < 4) ? A0 : A1;
        const __half* W    = (kt < 4) ? W0 : W1;
        int kc = (kt * 32) & 127;
        uint32_t aBase = smbase + (uint32_t)(s * ASTH) * 2;
        uint32_t bBase = smbase + (uint32_t)(2 * ASTH + s * BSTH) * 2;
#pragma unroll
        for (int i = 0; i < 2; i++) {
            int c = tid + i * 256;
            int row = c >> 2, q = c & 3;
            int grow = row0 + row;
            int ok = (grow < NN);
            const __half* p = srcA + (size_t)(ok ? grow : 0) * D + kc + q * 8;
            cpa16(aBase + (uint32_t)(row * SAH + q * 8) * 2, p, ok ? 16u : 0u);
        }
#pragma unroll
        for (int i = 0; i < 2; i++) {
            int c = tid + i * 256;
            int n = c >> 2, q = c & 3;
            const __half* p = W + (size_t)n * D + kc + q * 8;
            cpa16(bBase + (uint32_t)(n * SAH + q * 8) * 2, p, 16u);
        }
        asm volatile("cp.async.commit_group;" ::: "memory");
    };

    load_stage(0, 0);
    load_stage(1, 1);

#pragma unroll 1
    for (int kt = 0; kt < 8; kt++) {
        if (kt < 7) asm volatile("cp.async.wait_group 1;" ::: "memory");
        else        asm volatile("cp.async.wait_group 0;" ::: "memory");
        __syncthreads();

        int s = kt & 1;
        const __half* as_ = smh + s * ASTH;
        const __half* bs_ = smh + 2 * ASTH + s * BSTH;
#pragma unroll
        for (int ks = 0; ks < 32; ks += 16) {
            int kf = ks + 2 * cq;
            uint32_t bf[4][2];
#pragma unroll
            for (int ni = 0; ni < 4; ni++) {
                int n = wn * 32 + ni * 8 + r;
                bf[ni][0] = *(const uint32_t*)(bs_ + n * SAH + kf);
                bf[ni][1] = *(const uint32_t*)(bs_ + n * SAH + kf + 8);
            }
#pragma unroll
            for (int mi = 0; mi < 4; mi++) {
                int row = wm * 64 + mi * 16 + r;
                uint32_t a0 = *(const uint32_t*)(as_ + row * SAH + kf);
                uint32_t a1 = *(const uint32_t*)(as_ + (row + 8) * SAH + kf);
                uint32_t a2 = *(const uint32_t*)(as_ + row * SAH + kf + 8);
                uint32_t a3 = *(const uint32_t*)(as_ + (row + 8) * SAH + kf + 8);
#pragma unroll
                for (int ni = 0; ni < 4; ni++) {
                    asm volatile(
                        "mma.sync.aligned.m16n8k16.row.col.f32.f16.f16.f32 "
                        "{%0,%1,%2,%3}, {%4,%5,%6,%7}, {%8,%9}, {%0,%1,%2,%3};"
                        : "+f"(acc[mi][ni][0]), "+f"(acc[mi][ni][1]),
                          "+f"(acc[mi][ni][2]), "+f"(acc[mi][ni][3])
                        : "r"(a0), "r"(a1), "r"(a2), "r"(a3),
                          "r"(bf[ni][0]), "r"(bf[ni][1]));
                }
            }
        }
        __syncthreads();
        if (kt + 2 < 8) load_stage(s, kt + 2);
    }

#pragma unroll
    for (int mi = 0; mi < 4; mi++) {
        int r0g = row0 + wm * 64 + mi * 16 + r;
        int r1g = r0g + 8;
#pragma unroll
        for (int ni = 0; ni < 4; ni++) {
            int col = wn * 32 + ni * 8 + 2 * cq;
            float bz0 = bias[col], bz1 = bias[col + 1];
            float v0 = fmaxf(acc[mi][ni][0] + bz0, 0.f);
            float v1 = fmaxf(acc[mi][ni][1] + bz1, 0.f);
            float v2 = fmaxf(acc[mi][ni][2] + bz0, 0.f);
            float v3 = fmaxf(acc[mi][ni][3] + bz1, 0.f);
            if (r0g < NN) {
                __half2 h = __floats2half2_rn(v0, v1);
                *(uint32_t*)(out16 + (size_t)r0g * D + col) = *(uint32_t*)&h;
            }
            if (r1g < NN) {
                __half2 h = __floats2half2_rn(v2, v3);
                *(uint32_t*)(out16 + (size_t)r1g * D + col) = *(uint32_t*)&h;
            }
        }
    }
}

// ---------------- fused pooling + layer3 head + linear ----------------------
__global__ __launch_bounds__(128) void k_poolfinal(
    const float* __restrict__ W3rel,
    const float* __restrict__ W3root,
    const float* __restrict__ b3,
    const float* __restrict__ Wl,
    const float* __restrict__ bl,
    float* __restrict__ out)
{
    __shared__ float pa[128], ph[128], t[128];
    int g = blockIdx.x, n = threadIdx.x;
    int beg = g_gstart[g], end = g_gstart[g + 1];
    float sa = 0.f, sh = 0.f;
    for (int node = beg; node < end; node++) {
        sa += __half2float(g_agg16[(size_t)node * D + n]);
        sh += __half2float(g_h216[(size_t)node * D + n]);
    }
    int cnt = end - beg;
    float cinv = 1.0f / (float)max(cnt, 1);
    float bsel = (cnt > 0) ? 1.0f : 0.0f;
    pa[n] = sa * cinv;
    ph[n] = sh * cinv;
    __syncthreads();
    float acc = b3[n] * bsel;
#pragma unroll 8
    for (int k = 0; k < 128; k++)
        acc += pa[k] * W3rel[k * D + n] + ph[k] * W3root[k * D + n];
    t[n] = acc;
    __syncthreads();
    if (n < DOUT) {
        float o = bl[n];
#pragma unroll 8
        for (int k = 0; k < 128; k++)
            o += t[k] * Wl[k * DOUT + n];
        out[g * DOUT + n] = o;
    }
}

// ---------------- launcher ----------------
extern "C" void kernel_launch(void* const* d_in, const int* in_sizes, int n_in,
                              void* d_out, int out_size) {
    const float* x      = (const float*)d_in[0];
    const int*   ei     = (const int*)d_in[1];
    const int*   batch  = (const int*)d_in[2];
    const float* W1rel  = (const float*)d_in[3];
    const float* b1     = (const float*)d_in[4];
    const float* W1root = (const float*)d_in[5];
    const float* W2rel  = (const float*)d_in[6];
    const float* b2     = (const float*)d_in[7];
    const float* W2root = (const float*)d_in[8];
    const float* W3rel  = (const float*)d_in[9];
    const float* b3     = (const float*)d_in[10];
    const float* W3root = (const float*)d_in[11];
    const float* Wl     = (const float*)d_in[12];
    const float* bl     = (const float*)d_in[13];
    float*       out    = (float*)d_out;

    __half *x16, *h116, *h216, *agg16, *w16;
    cudaGetSymbolAddress((void**)&x16, g_x16);
    cudaGetSymbolAddress((void**)&h116, g_h116);
    cudaGetSymbolAddress((void**)&h216, g_h216);
    cudaGetSymbolAddress((void**)&agg16, g_agg16);
    cudaGetSymbolAddress((void**)&w16, g_w16);

    static int smem_set = 0;
    if (!smem_set) {
        cudaFuncSetAttribute(k_gemm16, cudaFuncAttributeMaxDynamicSharedMemorySize, GEMM_SMEM);
        smem_set = 1;
    }

    const int TB = 256;
    int gbE = (NE + TB - 1) / TB;
    int gbW = (NN * 32 + TB - 1) / TB;
    int gbM = (NN + 127) / 128;

    k_setup<<<GB_SETUP, TB>>>(ei, x, W1rel, W1root, W2rel, W2root, batch);
    k_scan<<<SCAN_BLOCKS, 1024>>>();
    k_fill<<<gbE, TB>>>(ei);
    // 4: layer-1 aggregation (profiled slot)
    k_agg16<<<gbW, TB>>>(x16);
    k_gemm16<<<gbM, TB, GEMM_SMEM>>>(agg16, x16, w16, w16 + D * D, b1, h116);
    k_agg16<<<gbW, TB>>>(h116);
    k_gemm16<<<gbM, TB, GEMM_SMEM>>>(agg16, h116, w16 + 2 * D * D, w16 + 3 * D * D, b2, h216);
    k_agg16<<<gbW, TB>>>(h216);
    k_poolfinal<<<NG, 128>>>(W3rel, W3root, b3, Wl, bl, out);
}